// round 3
// baseline (speedup 1.0000x reference)
#include <cuda_runtime.h>

// LFQ: z [4,14,32,32] f32. Codebook = all +-1 bit patterns, so the T=0.01
// softmax factorizes per bit. A bit is "soft" only when sigma(-400|z_d|) is
// nonzero in fp32 (|z| <~ 0.22, P~0.18), so each token has only 2^nsoft ~ 8
// nonzero-probability codes -> enumerate them directly and scatter into a
// u64 fixed-point histogram (integer atomics = bit-deterministic).
//
// Output layout (f32): quantized[57344], commit_loss, entropy_aux_loss,
// codebook_usage, idx_flat[4096].

#define N_TOK 4096
#define DIM   14
#define HW    1024
#define NE    16384
#define QELEMS (N_TOK * DIM)       // 57344
#define FIXSCALE 1099511627776.0   // 2^40

__device__ unsigned long long g_hist[NE];
__device__ unsigned int       g_bitset[2048];   // token-index presence bits
__device__ float              g_wcom[128];      // per-warp commit partials
__device__ float              g_went[128];      // per-warp entropy partials

// ---------------------------------------------------------------------------
__global__ void k_zero() {
    int i = blockIdx.x * blockDim.x + threadIdx.x;   // 64 x 256 = 16384
    g_hist[i] = 0ull;
    if (i < 2048) g_bitset[i] = 0u;
}

// ---------------------------------------------------------------------------
// 128 blocks x 32 threads; thread = one token. Coalesced z/q/idx traffic.
__global__ void k_token(const float* __restrict__ z, float* __restrict__ out) {
    int t  = blockIdx.x * 32 + threadIdx.x;
    int b  = t >> 10;
    int hw = t & 1023;
    const float* zp = z   + b * (DIM * HW) + hw;
    float*       qp = out + b * (DIM * HW) + hw;

    float com = 0.f, ent = 0.f, pbase = 1.f;
    unsigned idx = 0u, nsoft = 0u;
    float    ratio[DIM];
    unsigned pos[DIM];

    #pragma unroll
    for (int d = 0; d < DIM; d++) {
        float zv = zp[d * HW];
        float q  = (zv > 0.f) ? 1.f : -1.f;
        qp[d * HW] = q;
        float df = zv - q;
        com += df * df;
        if (zv > 0.f) idx |= (1u << d);

        float ax = 400.f * fabsf(zv);
        float pc = 1.f / (1.f + expf(-ax));   // prob of chosen bit
        float po = 1.f / (1.f + expf(ax));    // prob of flipped bit (0 if hard)
        pbase *= pc;

        float em   = expf(-ax);
        float sp   = log1pf(em);
        float pmin = em / (1.f + em);
        ent += sp + pmin * ax;                // exact binary entropy term

        if (po > 0.f) { ratio[nsoft] = po / pc; pos[nsoft] = d; nsoft++; }
    }

    out[QELEMS + 3 + t] = (float)idx;
    atomicOr(&g_bitset[idx >> 5], 1u << (idx & 31u));

    // warp-reduce commit/entropy -> per-warp partials (fixed order downstream)
    #pragma unroll
    for (int o = 16; o; o >>= 1) {
        com += __shfl_down_sync(0xffffffffu, com, o);
        ent += __shfl_down_sync(0xffffffffu, ent, o);
    }
    if (threadIdx.x == 0) { g_wcom[blockIdx.x] = com; g_went[blockIdx.x] = ent; }

    // enumerate the 2^nsoft nonzero codes
    unsigned total = 1u << nsoft;
    for (unsigned s = 0; s < total; s++) {
        float p = pbase;
        unsigned code = idx;
        unsigned ss = s;
        while (ss) {
            int j = __ffs(ss) - 1;
            ss &= ss - 1u;
            p *= ratio[j];
            code ^= (1u << pos[j]);
        }
        unsigned long long f = __double2ull_rn((double)p * FIXSCALE);
        if (f) atomicAdd(&g_hist[code], f);
    }
}

// ---------------------------------------------------------------------------
// One block, 1024 threads: ring-leftover marking (shared bitset + run-dedup),
// histogram entropy, partial reductions, final scalars.
__global__ void k_finish(const int* __restrict__ used, float* __restrict__ out) {
    __shared__ unsigned s_bs[2048];
    __shared__ float redc[1024];
    __shared__ float rede[1024];
    __shared__ float reda[1024];
    __shared__ int   redn[1024];
    int tid = threadIdx.x;

    s_bs[tid] = 0u; s_bs[tid + 1024] = 0u;
    __syncthreads();

    // mark used[4096:65536): run-length dedup kills same-address contention
    {
        unsigned curw = 0xffffffffu, curm = 0u;
        for (int k = tid; k < 65536 - N_TOK; k += 1024) {
            unsigned v = ((unsigned)used[N_TOK + k]) & 65535u;
            unsigned w = v >> 5, mm = 1u << (v & 31u);
            if (w == curw) curm |= mm;
            else {
                if (curw != 0xffffffffu) atomicOr(&s_bs[curw], curm);
                curw = w; curm = mm;
            }
        }
        if (curw != 0xffffffffu) atomicOr(&s_bs[curw], curm);
    }

    // histogram -> avg-probs entropy (fixed per-thread set: deterministic)
    float ae = 0.f;
    #pragma unroll
    for (int k = 0; k < 16; k++) {
        int j = k * 1024 + tid;
        unsigned long long hv = g_hist[j];
        if (hv) {
            float avg = (float)((double)hv * (1.0 / FIXSCALE) * (1.0 / 4096.0));
            ae += -avg * logf(avg + 1e-5f);
        }
    }

    float cs = 0.f, es = 0.f;
    if (tid < 128) { cs = g_wcom[tid]; es = g_went[tid]; }

    __syncthreads();
    int cnt = __popc(s_bs[tid] | g_bitset[tid]) +
              __popc(s_bs[tid + 1024] | g_bitset[tid + 1024]);

    redc[tid] = cs; rede[tid] = es; reda[tid] = ae; redn[tid] = cnt;
    __syncthreads();
    for (int o = 512; o; o >>= 1) {
        if (tid < o) {
            redc[tid] += redc[tid + o];
            rede[tid] += rede[tid + o];
            reda[tid] += reda[tid + o];
            redn[tid] += redn[tid + o];
        }
        __syncthreads();
    }
    if (tid == 0) {
        float commit   = 0.25f * redc[0] / (float)QELEMS;
        float sample_e = rede[0] / (float)N_TOK;
        float loss     = 0.1f * (sample_e - reda[0]);
        float usage    = (float)redn[0] / (float)NE;
        out[QELEMS + 0] = commit;
        out[QELEMS + 1] = loss;
        out[QELEMS + 2] = usage;
    }
}

// ---------------------------------------------------------------------------
extern "C" void kernel_launch(void* const* d_in, const int* in_sizes, int n_in,
                              void* d_out, int out_size) {
    const float* z    = (const float*)d_in[0];
    const int*   used = (const int*)d_in[2];
    float*       out  = (float*)d_out;

    k_zero<<<64, 256>>>();
    k_token<<<128, 32>>>(z, out);
    k_finish<<<1, 1024>>>(used, out);
}

// round 4
// speedup vs baseline: 1.5405x; 1.5405x over previous
#include <cuda_runtime.h>

// LFQ: z [4,14,32,32] f32. Codebook = all +-1 bit patterns -> T=0.01 softmax
// factorizes per bit. A bit is "soft" only when its flipped-bit probability
// po = 1/(1+expf(400|z_d|)) is nonzero in fp32 (|z| <~ 0.22, P~0.17), so a
// token has only 2^nsoft (~8) nonzero-probability codes. Enumerate them with
// STATIC indexing (mask-driven unrolled expansion -> registers, no spills)
// and scatter into a u64 fixed-point histogram (integer atomics commute =>
// bit-deterministic).
//
// Output (f32): quantized[57344], commit, entropy_loss, usage, idx_flat[4096].

#define N_TOK 4096
#define DIM   14
#define HW    1024
#define NE    16384
#define QELEMS (N_TOK * DIM)       // 57344
#define FIXSCALE 1099511627776.0   // 2^40
#define FULLM 0xffffffffu

__device__ unsigned long long g_hist[NE];
__device__ unsigned int       g_bitset[2048];
__device__ float              g_wcom[128];
__device__ float              g_went[128];

// ---------------------------------------------------------------------------
__global__ void k_zero() {
    int i = blockIdx.x * blockDim.x + threadIdx.x;   // 64 x 256
    g_hist[i] = 0ull;
    if (i < 2048) g_bitset[i] = 0u;
}

// ---------------------------------------------------------------------------
__device__ __forceinline__ void emit_subsets_strided(
    unsigned m, float pbase, unsigned idx, const float* __restrict__ ratio,
    unsigned start, unsigned stride)
{
    unsigned total = 1u << __popc(m);
    for (unsigned s = start; s < total; s += stride) {
        float p = pbase;
        unsigned code = idx;
        unsigned sb = s;
        #pragma unroll
        for (int d = 0; d < DIM; d++) {
            if ((m >> d) & 1u) {
                if (sb & 1u) { p *= ratio[d]; code ^= (1u << d); }
                sb >>= 1u;
            }
        }
        unsigned long long f = __double2ull_rn((double)p * FIXSCALE);
        if (f) atomicAdd(&g_hist[code], f);
    }
}

// Blocks 0..15: token work (8 warps/block, thread = token).
// Blocks 16..23: ring-buffer leftover marking via shared bitset.
__global__ void k_main(const float* __restrict__ z, const int* __restrict__ used,
                       float* __restrict__ out) {
    int blk = blockIdx.x;
    int tid = threadIdx.x;

    if (blk < 16) {
        int warp = tid >> 5, lane = tid & 31;
        int wg = blk * 8 + warp;           // global warp id 0..127
        int t  = wg * 32 + lane;           // token id
        int b  = t >> 10;
        int hw = t & 1023;
        const float* zp = z   + b * (DIM * HW) + hw;
        float*       qp = out + b * (DIM * HW) + hw;

        float com = 0.f, ent = 0.f, pbase = 1.f;
        unsigned idx = 0u, mask = 0u;
        float ratio[DIM];

        #pragma unroll
        for (int d = 0; d < DIM; d++) {
            float zv = zp[d * HW];
            float q  = (zv > 0.f) ? 1.f : -1.f;
            qp[d * HW] = q;
            float df = zv - q;
            com += df * df;
            if (zv > 0.f) idx |= (1u << d);

            float ax = 400.f * fabsf(zv);
            float pc = 1.f / (1.f + expf(-ax));
            float po = 1.f / (1.f + expf(ax));
            pbase *= pc;
            ratio[d] = po / pc;
            if (po > 0.f) mask |= (1u << d);

            float em   = expf(-ax);
            float sp   = log1pf(em);
            float pmin = em / (1.f + em);
            ent += sp + pmin * ax;
        }

        out[QELEMS + 3 + t] = (float)idx;
        atomicOr(&g_bitset[idx >> 5], 1u << (idx & 31u));

        #pragma unroll
        for (int o = 16; o; o >>= 1) {
            com += __shfl_down_sync(FULLM, com, o);
            ent += __shfl_down_sync(FULLM, ent, o);
        }
        if (lane == 0) { g_wcom[wg] = com; g_went[wg] = ent; }

        unsigned nsoft = __popc(mask);
        if (nsoft < 6)
            emit_subsets_strided(mask, pbase, idx, ratio, 0u, 1u);

        // heavy tokens: broadcast state, all 32 lanes share the subsets
        unsigned heavy = __ballot_sync(FULLM, nsoft >= 6);
        while (heavy) {
            int L = __ffs(heavy) - 1;
            heavy &= heavy - 1u;
            unsigned hm   = __shfl_sync(FULLM, mask,  L);
            float    hp   = __shfl_sync(FULLM, pbase, L);
            unsigned hidx = __shfl_sync(FULLM, idx,   L);
            float hr[DIM];
            #pragma unroll
            for (int d = 0; d < DIM; d++) hr[d] = __shfl_sync(FULLM, ratio[d], L);
            emit_subsets_strided(hm, hp, hidx, hr, (unsigned)lane, 32u);
        }
    } else {
        // marking blocks: used[4096:65536), 7680 elements per block
        __shared__ unsigned s_bs[2048];
        for (int i = tid; i < 2048; i += 256) s_bs[i] = 0u;
        __syncthreads();

        const int* src = used + N_TOK + (blk - 16) * 7680;
        unsigned curw = 0xffffffffu, curm = 0u;
        for (int k = tid; k < 7680; k += 256) {
            unsigned v = ((unsigned)src[k]) & 65535u;
            unsigned w = v >> 5, mm = 1u << (v & 31u);
            if (w == curw) curm |= mm;
            else {
                if (curw != 0xffffffffu) atomicOr(&s_bs[curw], curm);
                curw = w; curm = mm;
            }
        }
        if (curw != 0xffffffffu) atomicOr(&s_bs[curw], curm);
        __syncthreads();

        for (int i = tid; i < 2048; i += 256) {
            unsigned v = s_bs[i];
            if (v) atomicOr(&g_bitset[i], v);
        }
    }
}

// ---------------------------------------------------------------------------
__global__ void k_finish(float* __restrict__ out) {
    __shared__ float redc[1024];
    __shared__ float rede[1024];
    __shared__ float reda[1024];
    __shared__ int   redn[1024];
    int tid = threadIdx.x;

    float ae = 0.f;
    #pragma unroll
    for (int k = 0; k < 16; k++) {
        int j = k * 1024 + tid;            // fixed per-thread set: deterministic
        unsigned long long hv = g_hist[j];
        if (hv) {
            float avg = (float)((double)hv * (1.0 / FIXSCALE) * (1.0 / 4096.0));
            ae += -avg * logf(avg + 1e-5f);
        }
    }

    float cs = 0.f, es = 0.f;
    if (tid < 128) { cs = g_wcom[tid]; es = g_went[tid]; }

    int cnt = __popc(g_bitset[tid]) + __popc(g_bitset[tid + 1024]);

    redc[tid] = cs; rede[tid] = es; reda[tid] = ae; redn[tid] = cnt;
    __syncthreads();
    for (int o = 512; o; o >>= 1) {
        if (tid < o) {
            redc[tid] += redc[tid + o];
            rede[tid] += rede[tid + o];
            reda[tid] += reda[tid + o];
            redn[tid] += redn[tid + o];
        }
        __syncthreads();
    }
    if (tid == 0) {
        float commit   = 0.25f * redc[0] / (float)QELEMS;
        float sample_e = rede[0] / (float)N_TOK;
        float loss     = 0.1f * (sample_e - reda[0]);
        float usage    = (float)redn[0] / (float)NE;
        out[QELEMS + 0] = commit;
        out[QELEMS + 1] = loss;
        out[QELEMS + 2] = usage;
    }
}

// ---------------------------------------------------------------------------
extern "C" void kernel_launch(void* const* d_in, const int* in_sizes, int n_in,
                              void* d_out, int out_size) {
    const float* z    = (const float*)d_in[0];
    const int*   used = (const int*)d_in[2];
    float*       out  = (float*)d_out;

    k_zero<<<64, 256>>>();
    k_main<<<24, 256>>>(z, used, out);
    k_finish<<<1, 1024>>>(out);
}

// round 5
// speedup vs baseline: 1.8947x; 1.2299x over previous
#include <cuda_runtime.h>

// LFQ: z [4,14,32,32] f32. Codebook = all +-1 bit patterns -> T=0.01 softmax
// factorizes per bit. With em = expf(-400|z_d|): chosen-bit prob pc=1/(1+em),
// flipped-bit prob po=em*pc, and flip ratio po/pc = em exactly. A bit is
// "soft" only when em > 0 in fp32, so a token has only 2^nsoft (~8) nonzero
// codes -> enumerate (static indexing, register-resident) and scatter into a
// u64 fixed-point histogram (integer atomics commute => bit-deterministic).
//
// Output (f32): quantized[57344], commit, entropy_loss, usage, idx_flat[4096].

#define N_TOK 4096
#define DIM   14
#define HW    1024
#define NE    16384
#define QELEMS (N_TOK * DIM)       // 57344
#define FIXSCALE 1099511627776.0   // 2^40
#define FULLM 0xffffffffu

struct State {
    unsigned long long hist[NE];   // fixed-point sum of probs per code
    unsigned int       bitset[2048];
};
__device__ State g_s;              // zeroed by one memset node per replay
__device__ float g_wcom[128];
__device__ float g_went[128];

// ---------------------------------------------------------------------------
__device__ __forceinline__ void emit_subsets_strided(
    unsigned m, float pbase, unsigned idx, const float* __restrict__ ratio,
    unsigned start, unsigned stride)
{
    unsigned total = 1u << __popc(m);
    for (unsigned s = start; s < total; s += stride) {
        float p = pbase;
        unsigned code = idx;
        unsigned sb = s;
        #pragma unroll
        for (int d = 0; d < DIM; d++) {
            if ((m >> d) & 1u) {
                if (sb & 1u) { p *= ratio[d]; code ^= (1u << d); }
                sb >>= 1u;
            }
        }
        unsigned long long f = __double2ull_rn((double)p * FIXSCALE);
        if (f) atomicAdd(&g_s.hist[code], f);
    }
}

// Blocks 0..63: token work (2 warps/block, thread = token).
// Blocks 64..95: ring-buffer leftover marking (1920 entries each).
__global__ void k_main(const float* __restrict__ z, const int* __restrict__ used,
                       float* __restrict__ out) {
    int blk = blockIdx.x;
    int tid = threadIdx.x;                 // 64 threads

    if (blk < 64) {
        int lane = tid & 31;
        int wg = blk * 2 + (tid >> 5);     // global warp id 0..127
        int t  = wg * 32 + lane;           // token id
        int b  = t >> 10;
        int hw = t & 1023;
        const float* zp = z   + b * (DIM * HW) + hw;
        float*       qp = out + b * (DIM * HW) + hw;

        float com = 0.f, ent = 0.f, pbase = 1.f;
        unsigned idx = 0u, mask = 0u;
        float ratio[DIM];

        #pragma unroll
        for (int d = 0; d < DIM; d++) {
            float zv = zp[d * HW];
            float q  = (zv > 0.f) ? 1.f : -1.f;
            qp[d * HW] = q;
            float df = zv - q;
            com += df * df;
            if (zv > 0.f) idx |= (1u << d);

            float ax = 400.f * fabsf(zv);
            float em = expf(-ax);              // == flip ratio po/pc
            float pc = 1.f / (1.f + em);
            float po = em * pc;
            pbase *= pc;
            ratio[d] = em;
            if (po > 0.f) mask |= (1u << d);

            ent += log1pf(em) + po * ax;       // exact binary entropy term
        }

        out[QELEMS + 3 + t] = (float)idx;
        atomicOr(&g_s.bitset[idx >> 5], 1u << (idx & 31u));

        #pragma unroll
        for (int o = 16; o; o >>= 1) {
            com += __shfl_down_sync(FULLM, com, o);
            ent += __shfl_down_sync(FULLM, ent, o);
        }
        if (lane == 0) { g_wcom[wg] = com; g_went[wg] = ent; }

        unsigned nsoft = __popc(mask);
        if (nsoft < 6)
            emit_subsets_strided(mask, pbase, idx, ratio, 0u, 1u);

        unsigned heavy = __ballot_sync(FULLM, nsoft >= 6);
        while (heavy) {
            int L = __ffs(heavy) - 1;
            heavy &= heavy - 1u;
            unsigned hm   = __shfl_sync(FULLM, mask,  L);
            float    hp   = __shfl_sync(FULLM, pbase, L);
            unsigned hidx = __shfl_sync(FULLM, idx,   L);
            float hr[DIM];
            #pragma unroll
            for (int d = 0; d < DIM; d++) hr[d] = __shfl_sync(FULLM, ratio[d], L);
            emit_subsets_strided(hm, hp, hidx, hr, (unsigned)lane, 32u);
        }
    } else {
        // marking: used[4096:65536), 32 blocks x 1920 elements
        __shared__ unsigned s_bs[2048];
        for (int i = tid; i < 2048; i += 64) s_bs[i] = 0u;
        __syncthreads();

        const int* src = used + N_TOK + (blk - 64) * 1920;
        unsigned curw = 0xffffffffu, curm = 0u;
        for (int k = tid; k < 1920; k += 64) {
            unsigned v = ((unsigned)src[k]) & 65535u;
            unsigned w = v >> 5, mm = 1u << (v & 31u);
            if (w == curw) curm |= mm;
            else {
                if (curw != 0xffffffffu) atomicOr(&s_bs[curw], curm);
                curw = w; curm = mm;
            }
        }
        if (curw != 0xffffffffu) atomicOr(&s_bs[curw], curm);
        __syncthreads();

        for (int i = tid; i < 2048; i += 64) {
            unsigned v = s_bs[i];
            if (v) atomicOr(&g_s.bitset[i], v);
        }
    }
}

// ---------------------------------------------------------------------------
__global__ void k_finish(float* __restrict__ out) {
    __shared__ float redc[1024];
    __shared__ float rede[1024];
    __shared__ float reda[1024];
    __shared__ int   redn[1024];
    int tid = threadIdx.x;

    float ae = 0.f;
    #pragma unroll
    for (int k = 0; k < 16; k++) {
        int j = k * 1024 + tid;            // fixed per-thread set: deterministic
        unsigned long long hv = g_s.hist[j];
        if (hv) {
            float avg = (float)((double)hv * (1.0 / FIXSCALE) * (1.0 / 4096.0));
            ae += -avg * logf(avg + 1e-5f);
        }
    }

    float cs = 0.f, es = 0.f;
    if (tid < 128) { cs = g_wcom[tid]; es = g_went[tid]; }

    int cnt = __popc(g_s.bitset[tid]) + __popc(g_s.bitset[tid + 1024]);

    redc[tid] = cs; rede[tid] = es; reda[tid] = ae; redn[tid] = cnt;
    __syncthreads();
    for (int o = 512; o; o >>= 1) {
        if (tid < o) {
            redc[tid] += redc[tid + o];
            rede[tid] += rede[tid + o];
            reda[tid] += reda[tid + o];
            redn[tid] += redn[tid + o];
        }
        __syncthreads();
    }
    if (tid == 0) {
        float commit   = 0.25f * redc[0] / (float)QELEMS;
        float sample_e = rede[0] / (float)N_TOK;
        float loss     = 0.1f * (sample_e - reda[0]);
        float usage    = (float)redn[0] / (float)NE;
        out[QELEMS + 0] = commit;
        out[QELEMS + 1] = loss;
        out[QELEMS + 2] = usage;
    }
}

// ---------------------------------------------------------------------------
extern "C" void kernel_launch(void* const* d_in, const int* in_sizes, int n_in,
                              void* d_out, int out_size) {
    const float* z    = (const float*)d_in[0];
    const int*   used = (const int*)d_in[2];
    float*       out  = (float*)d_out;

    static void* sp = nullptr;
    if (!sp) cudaGetSymbolAddress(&sp, g_s);

    cudaMemsetAsync(sp, 0, sizeof(State), 0);   // zero hist + bitset
    k_main<<<96, 64>>>(z, used, out);
    k_finish<<<1, 1024>>>(out);
}

// round 6
// speedup vs baseline: 4.7278x; 2.4953x over previous
#include <cuda_runtime.h>

// LFQ: z [4,14,32,32] f32. Codebook = all +-1 bit patterns -> T=0.01 softmax
// factorizes per bit. With em = expf(-400|z_d|): pc=1/(1+em), po=em*pc, and
// flip ratio po/pc = em exactly. A bit is "soft" only when em > 0 in fp32,
// so a token has only 2^nsoft (~8) nonzero codes -> enumerate and scatter
// into a u64 fixed-point histogram (integer atomics commute => deterministic).
//
// Output (f32): quantized[57344], commit, entropy_loss, usage, idx_flat[4096].

#define N_TOK 4096
#define DIM   14
#define HW    1024
#define NE    16384
#define QELEMS (N_TOK * DIM)       // 57344
#define FIXSCALE 1099511627776.0   // 2^40
#define FULLM 0xffffffffu

struct State {
    unsigned long long hist[NE];
    unsigned int       bitset[2048];
    unsigned int       ticket;
};
__device__ State g_s;              // zeroed by one memset node per replay
__device__ float g_wcom[128];
__device__ float g_went[128];
__device__ float g_pae[64];        // per-block avg-entropy partials
__device__ int   g_pcnt[64];       // per-block popcount partials
__device__ float g_pce[2];         // block-0 commit/entropy sums

// ---------------------------------------------------------------------------
__device__ __forceinline__ void emit_subsets_strided(
    unsigned m, float pbase, unsigned idx, const float* __restrict__ ratio,
    unsigned start, unsigned stride)
{
    unsigned total = 1u << __popc(m);
    for (unsigned s = start; s < total; s += stride) {
        float p = pbase;
        unsigned code = idx;
        unsigned sb = s;
        #pragma unroll
        for (int d = 0; d < DIM; d++) {
            if ((m >> d) & 1u) {
                if (sb & 1u) { p *= ratio[d]; code ^= (1u << d); }
                sb >>= 1u;
            }
        }
        unsigned long long f = __double2ull_rn((double)p * FIXSCALE);
        if (f) atomicAdd(&g_s.hist[code], f);
    }
}

// Blocks 0..63: token work (2 warps, thread = token).
// Blocks 64..223: ring-buffer leftover marking (384 entries each).
__global__ void k_main(const float* __restrict__ z, const int* __restrict__ used,
                       float* __restrict__ out) {
    int blk = blockIdx.x;
    int tid = threadIdx.x;                 // 64 threads

    if (blk < 64) {
        int lane = tid & 31;
        int wg = blk * 2 + (tid >> 5);     // global warp id 0..127
        int t  = wg * 32 + lane;
        int b  = t >> 10;
        int hw = t & 1023;
        const float* zp = z   + b * (DIM * HW) + hw;
        float*       qp = out + b * (DIM * HW) + hw;

        float com = 0.f, ent = 0.f, pbase = 1.f;
        unsigned idx = 0u, mask = 0u;
        float ratio[DIM];

        #pragma unroll
        for (int d = 0; d < DIM; d++) {
            float zv = zp[d * HW];
            float q  = (zv > 0.f) ? 1.f : -1.f;
            qp[d * HW] = q;
            float df = zv - q;
            com += df * df;
            if (zv > 0.f) idx |= (1u << d);

            float ax = 400.f * fabsf(zv);
            float em = expf(-ax);              // == flip ratio
            float pc = 1.f / (1.f + em);
            float po = em * pc;
            pbase *= pc;
            ratio[d] = em;
            if (po > 0.f) mask |= (1u << d);

            ent += log1pf(em) + po * ax;
        }

        out[QELEMS + 3 + t] = (float)idx;
        atomicOr(&g_s.bitset[idx >> 5], 1u << (idx & 31u));

        #pragma unroll
        for (int o = 16; o; o >>= 1) {
            com += __shfl_down_sync(FULLM, com, o);
            ent += __shfl_down_sync(FULLM, ent, o);
        }
        if (lane == 0) { g_wcom[wg] = com; g_went[wg] = ent; }

        unsigned nsoft = __popc(mask);
        if (nsoft < 6)
            emit_subsets_strided(mask, pbase, idx, ratio, 0u, 1u);

        unsigned heavy = __ballot_sync(FULLM, nsoft >= 6);
        while (heavy) {
            int L = __ffs(heavy) - 1;
            heavy &= heavy - 1u;
            unsigned hm   = __shfl_sync(FULLM, mask,  L);
            float    hp   = __shfl_sync(FULLM, pbase, L);
            unsigned hidx = __shfl_sync(FULLM, idx,   L);
            float hr[DIM];
            #pragma unroll
            for (int d = 0; d < DIM; d++) hr[d] = __shfl_sync(FULLM, ratio[d], L);
            emit_subsets_strided(hm, hp, hidx, hr, (unsigned)lane, 32u);
        }
    } else {
        // marking: used[4096:65536) = 61440 entries, 160 blocks x 384
        __shared__ unsigned s_bs[2048];
        for (int i = tid; i < 2048; i += 64) s_bs[i] = 0u;
        __syncthreads();

        const int* src = used + N_TOK + (blk - 64) * 384;
        unsigned curw = 0xffffffffu, curm = 0u;
        #pragma unroll
        for (int it = 0; it < 6; it++) {
            unsigned v = ((unsigned)src[tid + it * 64]) & 65535u;
            unsigned w = v >> 5, mm = 1u << (v & 31u);
            if (w == curw) curm |= mm;
            else {
                if (curw != 0xffffffffu) atomicOr(&s_bs[curw], curm);
                curw = w; curm = mm;
            }
        }
        if (curw != 0xffffffffu) atomicOr(&s_bs[curw], curm);
        __syncthreads();

        for (int i = tid; i < 2048; i += 64) {
            unsigned v = s_bs[i];
            if (v) atomicOr(&g_s.bitset[i], v);
        }
    }
}

// ---------------------------------------------------------------------------
// 64 blocks x 256 threads. Block g: codes [g*256,(g+1)*256) entropy, 32
// bitset words popcount; block 0 also folds 128 commit/ent partials.
// Last block (ticket) reduces the 64 fixed-slot partials -> scalars.
__global__ void k_reduce(float* __restrict__ out) {
    __shared__ float reda[256];
    __shared__ int   redn[256];
    int tid = threadIdx.x;
    int g   = blockIdx.x;

    int j = g * 256 + tid;
    unsigned long long hv = g_s.hist[j];
    float ae = 0.f;
    if (hv) {
        float avg = (float)((double)hv * (1.0 / FIXSCALE) * (1.0 / 4096.0));
        ae = -avg * logf(avg + 1e-5f);
    }
    int cnt = (tid < 32) ? __popc(g_s.bitset[g * 32 + tid]) : 0;

    float ce = 0.f;
    if (g == 0 && tid < 256) {
        // 128 commit + 128 ent partials: tid<128 -> commit, else ent
        ce = (tid < 128) ? g_wcom[tid] : g_went[tid - 128];
    }

    reda[tid] = ae; redn[tid] = cnt;
    __syncthreads();
    for (int o = 128; o; o >>= 1) {
        if (tid < o) { reda[tid] += reda[tid + o]; redn[tid] += redn[tid + o]; }
        __syncthreads();
    }
    if (g == 0) {
        // fixed-order warp reductions of ce halves
        __shared__ float s_ce[2];
        float v = ce;
        #pragma unroll
        for (int o = 16; o; o >>= 1) v += __shfl_down_sync(FULLM, v, o);
        __shared__ float s_w[8];
        if ((tid & 31) == 0) s_w[tid >> 5] = v;
        __syncthreads();
        if (tid == 0)   s_ce[0] = s_w[0] + s_w[1] + s_w[2] + s_w[3];
        if (tid == 128) s_ce[1] = s_w[4] + s_w[5] + s_w[6] + s_w[7];
        __syncthreads();
        if (tid == 0) { g_pce[0] = s_ce[0]; g_pce[1] = s_ce[1]; }
    }
    if (tid == 0) { g_pae[g] = reda[0]; g_pcnt[g] = redn[0]; }

    // ticket: last block to finish performs the final reduce
    __shared__ int s_last;
    __threadfence();
    if (tid == 0) s_last = (atomicAdd(&g_s.ticket, 1u) == 63u);
    __syncthreads();
    if (s_last && tid < 64) {
        float a = g_pae[tid];
        int   c = g_pcnt[tid];
        #pragma unroll
        for (int o = 16; o; o >>= 1) {
            a += __shfl_down_sync(FULLM, a, o);
            c += __shfl_down_sync(FULLM, c, o);
        }
        __shared__ float s_a[2]; __shared__ int s_c[2];
        if ((tid & 31) == 0) { s_a[tid >> 5] = a; s_c[tid >> 5] = c; }
        __syncthreads();
        if (tid == 0) {
            float avg_e    = s_a[0] + s_a[1];
            int   used_cnt = s_c[0] + s_c[1];
            float commit   = 0.25f * g_pce[0] / (float)QELEMS;
            float sample_e = g_pce[1] / (float)N_TOK;
            out[QELEMS + 0] = commit;
            out[QELEMS + 1] = 0.1f * (sample_e - avg_e);
            out[QELEMS + 2] = (float)used_cnt / (float)NE;
        }
    }
}

// ---------------------------------------------------------------------------
extern "C" void kernel_launch(void* const* d_in, const int* in_sizes, int n_in,
                              void* d_out, int out_size) {
    const float* z    = (const float*)d_in[0];
    const int*   used = (const int*)d_in[2];
    float*       out  = (float*)d_out;

    static void* sp = nullptr;
    if (!sp) cudaGetSymbolAddress(&sp, g_s);

    cudaMemsetAsync(sp, 0, sizeof(State), 0);   // hist + bitset + ticket
    k_main<<<224, 64>>>(z, used, out);
    k_reduce<<<64, 256>>>(out);
}